// round 9
// baseline (speedup 1.0000x reference)
#include <cuda_runtime.h>
#include <cuda_fp16.h>
#include <cstdint>

// Problem constants
#define M_DIM   32
#define K_DIM   8192
#define N_DIM   8192
#define GROUP   128

#define NTILE   128                    // n-columns per CTA
#define SPLITS  8                      // split-K factor
#define KSPLIT  (K_DIM / SPLITS)       // 1024 k per CTA
#define NUM_KT  (KSPLIT / GROUP)       // 8 scale-groups per split
#define NCHUNK  (KSPLIT / 16)          // 64 k16 chunks per split
#define THREADS 256                    // 8 warps, each owns 16 n-columns
#define NTILES  (N_DIM / NTILE)        // 64

// A SMEM: [32 m][APITCH halves], k-permuted per octet (v0,v4,v1,v5,v2,v6,v3,v7)
// row stride 1032*2=2064 B == 16 mod 128 -> b-frag banks 4*lane4+(lane&3): conflict-free
#define APITCH  1032
#define A_BYTES (M_DIM * APITCH * 2)   // 66048

// Split-K partials + completion counters (static device scratch)
__device__ float    g_partial[SPLITS * M_DIM * N_DIM];
__device__ unsigned g_ctr[NTILES];

static __device__ __forceinline__ uint32_t lop3_and_or(uint32_t a, uint32_t b, uint32_t c) {
    uint32_t d;
    asm("lop3.b32 %0, %1, %2, %3, 0xEA;" : "=r"(d) : "r"(a), "r"(b), "r"(c));
    return d;
}

// Uniform per-lane dequant: lane j = lane&3 extracts nibble pair (j, j+4) of qword.
//  j even: h = ((q>>sh) & 0x000F000F) | 0x64006400 ; v = h*1 + (-1032)  = q-8 (exact)
//  j odd:  h = ((q>>sh) & 0x00F000F0) | 0x64006400 ; v = h*(1/16) + (-72) = q-8 (exact)
// then r = v * s (one fp16 rounding).
static __device__ __forceinline__ uint32_t dq2(uint32_t q, uint32_t sh, uint32_t mask,
                                               uint32_t cm2, uint32_t ca2, uint32_t s2) {
    uint32_t u = q >> sh;
    uint32_t h = lop3_and_or(u, mask, 0x64006400u);
    half2 v = __hfma2(*reinterpret_cast<half2*>(&h),
                      *reinterpret_cast<half2*>(&cm2),
                      *reinterpret_cast<half2*>(&ca2));
    half2 r = __hmul2(v, *reinterpret_cast<half2*>(&s2));
    return *reinterpret_cast<uint32_t*>(&r);
}

static __device__ __forceinline__ void mma_16816(float& d0, float& d1, float& d2, float& d3,
                                                 uint32_t a0, uint32_t a1, uint32_t a2,
                                                 uint32_t a3, uint32_t b0, uint32_t b1) {
    asm volatile(
        "mma.sync.aligned.m16n8k16.row.col.f32.f16.f16.f32 "
        "{%0,%1,%2,%3}, {%4,%5,%6,%7}, {%8,%9}, {%0,%1,%2,%3};\n"
        : "+f"(d0), "+f"(d1), "+f"(d2), "+f"(d3)
        : "r"(a0), "r"(a1), "r"(a2), "r"(a3), "r"(b0), "r"(b1));
}

__global__ void __launch_bounds__(THREADS, 3)
marlin_w4a16_fused(const float* __restrict__ A, const int* __restrict__ qw,
                   const float* __restrict__ scales, const float* __restrict__ bias,
                   float* __restrict__ out) {
    extern __shared__ __align__(16) char smem[];
    __shared__ unsigned s_old;
    half* a_sm = reinterpret_cast<half*>(smem);

    const int tid   = threadIdx.x;
    const int lane  = tid & 31;
    const int warp  = tid >> 5;            // 0..7
    const int lane4 = lane >> 2;           // 0..7

    // per-lane dequant constants
    const uint32_t sh   = (lane & 2) << 2;                        // 0 or 8
    const uint32_t mask = (lane & 1) ? 0x00F000F0u : 0x000F000Fu;
    const uint32_t cm2  = (lane & 1) ? 0x2C002C00u : 0x3C003C00u; // 1/16 : 1.0
    const uint32_t ca2  = (lane & 1) ? 0xD480D480u : 0xE408E408u; // -72 : -1032

    const int ntile = blockIdx.x;
    const int split = blockIdx.y;
    const int nbase = ntile * NTILE;
    const int k0    = split * KSPLIT;
    const int wcl   = warp * 16 + lane4;   // in-tile column of this thread's frag rows

    // ---- whole-A split-slice preload: fp32 -> fp16, k-permuted octets ----
    {
        const int am = tid >> 3;           // 0..31 m-row
        const int ao = tid & 7;            // 0..7
        const float* arow = A + (size_t)am * K_DIM + k0;
        half* drow = a_sm + (size_t)am * APITCH;
#pragma unroll
        for (int j = 0; j < 16; j++) {
            const int o = ao + 8 * j;      // octet 0..127
            float4 va = *reinterpret_cast<const float4*>(arow + o * 8);
            float4 vb = *reinterpret_cast<const float4*>(arow + o * 8 + 4);
            half2 p0 = __floats2half2_rn(va.x, vb.x);   // (v0, v4)
            half2 p1 = __floats2half2_rn(va.y, vb.y);   // (v1, v5)
            half2 p2 = __floats2half2_rn(va.z, vb.z);   // (v2, v6)
            half2 p3 = __floats2half2_rn(va.w, vb.w);   // (v3, v7)
            uint4 pk;
            pk.x = *reinterpret_cast<uint32_t*>(&p0);
            pk.y = *reinterpret_cast<uint32_t*>(&p1);
            pk.z = *reinterpret_cast<uint32_t*>(&p2);
            pk.w = *reinterpret_cast<uint32_t*>(&p3);
            *reinterpret_cast<uint4*>(drow + o * 8) = pk;
        }
    }

    // Accumulators: [m-tile t(4)][4]
    float acc[4][4];
#pragma unroll
    for (int t = 0; t < 4; t++)
#pragma unroll
        for (int r = 0; r < 4; r++) acc[t][r] = 0.0f;

    // ---- W pointer & depth-2 prefetch state ----
    // chunk c uses qweight rows (k0/8 + 2c, +2c+1), cols wcl + {0, 8}
    const int* qp = qw + (size_t)(k0 >> 3) * N_DIM + nbase + wcl;
    const float* sp = scales + (size_t)split * NUM_KT * N_DIM + nbase + wcl;

    uint32_t qc[4], qn[4];
    float sraw[2];
    {
        const int* r0 = qp;
        qc[0] = r0[0]; qc[1] = r0[8]; qc[2] = r0[N_DIM]; qc[3] = r0[N_DIM + 8];
        const int* r1 = qp + 2 * (size_t)N_DIM;
        qn[0] = r1[0]; qn[1] = r1[8]; qn[2] = r1[N_DIM]; qn[3] = r1[N_DIM + 8];
        sraw[0] = sp[0]; sraw[1] = sp[8];
    }

    __syncthreads();       // A tile resident (the only barrier before epilogue)

    uint32_t s2[2];

#pragma unroll 2
    for (int c = 0; c < NCHUNK; c++) {
        // kt boundary: convert prefetched scales, start next kt's scale loads
        if ((c & 7) == 0) {
#pragma unroll
            for (int r = 0; r < 2; r++) {
                half hs = __float2half_rn(sraw[r]);
                half2 p = __halves2half2(hs, hs);
                s2[r] = *reinterpret_cast<uint32_t*>(&p);
            }
            if (c + 8 < NCHUNK) {
                const float* spn = sp + (size_t)((c >> 3) + 1) * N_DIM;
                sraw[0] = spn[0]; sraw[1] = spn[8];
            }
        }

        // prefetch chunk c+2 (depth-2: overlaps two full chunk bodies)
        uint32_t qt[4];
        if (c + 2 < NCHUNK) {
            const int* r0 = qp + (size_t)(2 * (c + 2)) * N_DIM;
            qt[0] = r0[0]; qt[1] = r0[8]; qt[2] = r0[N_DIM]; qt[3] = r0[N_DIM + 8];
        }

        // dequant current chunk into a-frags
        uint32_t a0 = dq2(qc[0], sh, mask, cm2, ca2, s2[0]);  // (row n,   k pair j)
        uint32_t a1 = dq2(qc[1], sh, mask, cm2, ca2, s2[1]);  // (row n+8, k pair j)
        uint32_t a2 = dq2(qc[2], sh, mask, cm2, ca2, s2[0]);  // (row n,   k pair j+8)
        uint32_t a3 = dq2(qc[3], sh, mask, cm2, ca2, s2[1]);  // (row n+8, k pair j+8)

        // b-frags: permuted-k pairs, m = 8t + lane4, pair j = lane&3
        const half* bb = a_sm + (size_t)(c * 16 + (lane & 3) * 2);
        uint32_t b[4][2];
#pragma unroll
        for (int t = 0; t < 4; t++) {
            const half* bp = bb + (size_t)(8 * t + lane4) * APITCH;
            b[t][0] = *reinterpret_cast<const uint32_t*>(bp);
            b[t][1] = *reinterpret_cast<const uint32_t*>(bp + 8);
        }

#pragma unroll
        for (int t = 0; t < 4; t++)
            mma_16816(acc[t][0], acc[t][1], acc[t][2], acc[t][3],
                      a0, a1, a2, a3, b[t][0], b[t][1]);

#pragma unroll
        for (int i = 0; i < 4; i++) { qc[i] = qn[i]; qn[i] = qt[i]; }
    }

    // ---- write split partials: D[n][m] frag -> partial[split][m][n] ----
    float* pbase = g_partial + (size_t)split * M_DIM * N_DIM;
    {
        const int n_r = nbase + wcl;
#pragma unroll
        for (int t = 0; t < 4; t++) {
            const int m_c = 8 * t + 2 * (lane & 3);
            float* p = pbase + (size_t)m_c * N_DIM + n_r;
            p[0]         = acc[t][0];      // (n_r,   m_c)
            p[N_DIM]     = acc[t][1];      // (n_r,   m_c+1)
            p[8]         = acc[t][2];      // (n_r+8, m_c)
            p[N_DIM + 8] = acc[t][3];      // (n_r+8, m_c+1)
        }
    }

    // ---- fused reduction: last CTA per n-tile sums all splits + bias ----
    __threadfence();
    __syncthreads();
    if (tid == 0) s_old = atomicAdd(&g_ctr[ntile], 1);
    __syncthreads();

    if (s_old == SPLITS - 1) {
        __threadfence();
        const int n  = nbase + (tid & 127);     // 128 n-columns
        const int m0 = (tid >> 7) * 16;         // two m-halves
        const float bv = bias[n];
#pragma unroll 4
        for (int m = m0; m < m0 + 16; m++) {
            const float* p = g_partial + (size_t)m * N_DIM + n;
            float v = 0.0f;
#pragma unroll
            for (int sp2 = 0; sp2 < SPLITS; sp2++)
                v += p[(size_t)sp2 * (M_DIM * N_DIM)];
            out[(size_t)m * N_DIM + n] = v + bv;
        }
        __threadfence();
        if (tid == 0) g_ctr[ntile] = 0;    // reset for next launch
    }
}

extern "C" void kernel_launch(void* const* d_in, const int* in_sizes, int n_in,
                              void* d_out, int out_size) {
    const float* A      = (const float*)d_in[0];
    const int*   qw     = (const int*)d_in[1];
    const float* scales = (const float*)d_in[2];
    const float* bias   = (const float*)d_in[3];
    float* out = (float*)d_out;

    cudaFuncSetAttribute(marlin_w4a16_fused,
                         cudaFuncAttributeMaxDynamicSharedMemorySize, A_BYTES);
    dim3 grid(NTILES, SPLITS);
    marlin_w4a16_fused<<<grid, THREADS, A_BYTES>>>(A, qw, scales, bias, out);
}

// round 10
// speedup vs baseline: 1.7559x; 1.7559x over previous
#include <cuda_runtime.h>
#include <cuda_fp16.h>
#include <cstdint>

// Problem constants
#define M_DIM   32
#define K_DIM   8192
#define N_DIM   8192
#define GROUP   128

#define NTILE   256                    // n-columns per CTA
#define SPLITS  8                      // split-K factor
#define KSPLIT  (K_DIM / SPLITS)       // 1024 k per CTA
#define NUM_KT  (KSPLIT / GROUP)       // 8 k-tiles of 128
#define THREADS 256                    // 8 warps, each owns 32 n-columns
#define NTILES  (N_DIM / NTILE)        // 32

// Activation SMEM tile: [32 m][136 halves] per buffer, k-PERMUTED per octet:
//   octet o of row m at halves [o*8..o*8+7] = (v0,v4,v1,v5,v2,v6,v3,v7)
// row stride 272 B == 16 mod 128 -> b-frag banks 16*lane4 + 4*(lane&3): all distinct
#define APITCH  136
#define ABUF_HALVES (32 * APITCH)      // 4352 halves = 8704 B per buffer

// Split-K partials: [SPLITS][32][8192] fp32 (8 MB static device scratch)
__device__ float g_partial[SPLITS * M_DIM * N_DIM];

// lop3: (a & b) | c  -> immLut 0xEA
static __device__ __forceinline__ uint32_t lop3_and_or(uint32_t a, uint32_t b, uint32_t c) {
    uint32_t d;
    asm("lop3.b32 %0, %1, %2, %3, 0xEA;" : "=r"(d) : "r"(a), "r"(b), "r"(c));
    return d;
}

// Uniform per-lane dequant: lane j = lane&3 extracts nibble pair (j, j+4) of qword.
//  j even: h = ((q>>sh) & 0x000F000F) | 0x64006400 ; v = h*1 + (-1032)    = q-8 (exact)
//  j odd:  h = ((q>>sh) & 0x00F000F0) | 0x64006400 ; v = h*(1/16) + (-72) = q-8 (exact)
// then r = v * s (one fp16 rounding).
static __device__ __forceinline__ uint32_t dq2(uint32_t q, uint32_t sh, uint32_t mask,
                                               uint32_t cm2, uint32_t ca2, uint32_t s2) {
    uint32_t u = q >> sh;
    uint32_t h = lop3_and_or(u, mask, 0x64006400u);
    half2 v = __hfma2(*reinterpret_cast<half2*>(&h),
                      *reinterpret_cast<half2*>(&cm2),
                      *reinterpret_cast<half2*>(&ca2));
    half2 r = __hmul2(v, *reinterpret_cast<half2*>(&s2));
    return *reinterpret_cast<uint32_t*>(&r);
}

static __device__ __forceinline__ void mma_16816(float& d0, float& d1, float& d2, float& d3,
                                                 uint32_t a0, uint32_t a1, uint32_t a2,
                                                 uint32_t a3, uint32_t b0, uint32_t b1) {
    asm volatile(
        "mma.sync.aligned.m16n8k16.row.col.f32.f16.f16.f32 "
        "{%0,%1,%2,%3}, {%4,%5,%6,%7}, {%8,%9}, {%0,%1,%2,%3};\n"
        : "+f"(d0), "+f"(d1), "+f"(d2), "+f"(d3)
        : "r"(a0), "r"(a1), "r"(a2), "r"(a3), "r"(b0), "r"(b1));
}

__global__ void __launch_bounds__(THREADS, 2)
marlin_w4a16_main(const float* __restrict__ A, const int* __restrict__ qw,
                  const float* __restrict__ scales) {
    __shared__ __align__(16) half as2[2][ABUF_HALVES];

    const int tid   = threadIdx.x;
    const int lane  = tid & 31;
    const int warp  = tid >> 5;            // 0..7
    const int lane4 = lane >> 2;           // 0..7

    // per-lane dequant constants
    const uint32_t sh   = (lane & 2) << 2;                        // 0 or 8
    const uint32_t mask = (lane & 1) ? 0x00F000F0u : 0x000F000Fu;
    const uint32_t cm2  = (lane & 1) ? 0x2C002C00u : 0x3C003C00u; // 1/16 : 1.0
    const uint32_t ca2  = (lane & 1) ? 0xD480D480u : 0xE408E408u; // -72 : -1032

    const int nbase = blockIdx.x * NTILE;  // CTA n-range
    const int split = blockIdx.y;          // k-split index
    const int k0    = split * KSPLIT;
    const int c0    = nbase + warp * 32 + lane4;   // this thread's frag-row-0 column

    // Staging coords: 32 rows x 8 threads/row, 2 octet-pairs (16 k) each... 2 octets/thread
    const int sm = tid >> 3;               // 0..31 (m row)
    const int so = tid & 7;                // 0..7
    const float* a_row = A + (size_t)sm * K_DIM + k0;

    // Accumulators: [a-frag f(2)][m-tile t(4)][4]
    float acc[2][4][4];
#pragma unroll
    for (int f = 0; f < 2; f++)
#pragma unroll
        for (int t = 0; t < 4; t++)
#pragma unroll
            for (int r = 0; r < 4; r++) acc[f][t][r] = 0.0f;

    const int* qcol = qw + c0;             // + row*N_DIM per k-row-of-8

#pragma unroll 1
    for (int kt = 0; kt < NUM_KT; kt++) {
        const int buf = kt & 1;

        // ---- stage A[0:32][kt*128 .. +128): fp32 -> fp16, k-permuted octets ----
        {
            const float* src = a_row + kt * GROUP;
            half* dst = &as2[buf][sm * APITCH];
#pragma unroll
            for (int jo = 0; jo < 2; jo++) {
                const int o = so + 8 * jo;     // octet 0..15
                float4 va = *reinterpret_cast<const float4*>(src + o * 8);
                float4 vb = *reinterpret_cast<const float4*>(src + o * 8 + 4);
                half2 p0 = __floats2half2_rn(va.x, vb.x);   // (v0, v4)
                half2 p1 = __floats2half2_rn(va.y, vb.y);   // (v1, v5)
                half2 p2 = __floats2half2_rn(va.z, vb.z);   // (v2, v6)
                half2 p3 = __floats2half2_rn(va.w, vb.w);   // (v3, v7)
                uint4 pk;
                pk.x = *reinterpret_cast<uint32_t*>(&p0);
                pk.y = *reinterpret_cast<uint32_t*>(&p1);
                pk.z = *reinterpret_cast<uint32_t*>(&p2);
                pk.w = *reinterpret_cast<uint32_t*>(&p3);
                *reinterpret_cast<uint4*>(dst + o * 8) = pk;
            }
        }
        __syncthreads();

        // ---- per-group scales for this thread's 4 n-columns ----
        uint32_t s2[4];
        {
            const float* sp = scales + (size_t)(split * NUM_KT + kt) * N_DIM + c0;
#pragma unroll
            for (int r = 0; r < 4; r++) {
                half hs = __float2half_rn(sp[r * 8]);
                half2 p = __halves2half2(hs, hs);
                s2[r] = *reinterpret_cast<uint32_t*>(&p);
            }
        }

        const int qrow0 = (k0 + kt * GROUP) >> 3;   // first k-row-of-8 in this tile

        // ---- 8 chunks of k16 (fully unrolled: ptxas batches the 64 LDGs) ----
#pragma unroll
        for (int ch = 0; ch < 8; ch++) {
            const int* qr0 = qcol + (size_t)(qrow0 + 2 * ch) * N_DIM;
            const int* qr1 = qr0 + N_DIM;
            // W loads (4-lane broadcast each): rows {2ch, 2ch+1} x col offsets {0,8,16,24}
            uint32_t q00 = (uint32_t)qr0[0],  q01 = (uint32_t)qr0[8];
            uint32_t q02 = (uint32_t)qr0[16], q03 = (uint32_t)qr0[24];
            uint32_t q10 = (uint32_t)qr1[0],  q11 = (uint32_t)qr1[8];
            uint32_t q12 = (uint32_t)qr1[16], q13 = (uint32_t)qr1[24];

            // a-frags (dequant straight into fragment registers)
            uint32_t a[2][4];
            a[0][0] = dq2(q00, sh, mask, cm2, ca2, s2[0]);  // row n,    k pair j
            a[0][1] = dq2(q01, sh, mask, cm2, ca2, s2[1]);  // row n+8
            a[0][2] = dq2(q10, sh, mask, cm2, ca2, s2[0]);  // row n,    k pair j+8
            a[0][3] = dq2(q11, sh, mask, cm2, ca2, s2[1]);  // row n+8
            a[1][0] = dq2(q02, sh, mask, cm2, ca2, s2[2]);
            a[1][1] = dq2(q03, sh, mask, cm2, ca2, s2[3]);
            a[1][2] = dq2(q12, sh, mask, cm2, ca2, s2[2]);
            a[1][3] = dq2(q13, sh, mask, cm2, ca2, s2[3]);

            // b-frags: permuted-k pairs, m = 8t + lane4, pair j = lane&3
            const half* bb = &as2[buf][(size_t)(ch * 16 + (lane & 3) * 2)];
            uint32_t b[4][2];
#pragma unroll
            for (int t = 0; t < 4; t++) {
                const half* bp = bb + (size_t)(8 * t + lane4) * APITCH;
                b[t][0] = *reinterpret_cast<const uint32_t*>(bp);       // octet 2ch
                b[t][1] = *reinterpret_cast<const uint32_t*>(bp + 8);   // octet 2ch+1
            }

#pragma unroll
            for (int f = 0; f < 2; f++)
#pragma unroll
                for (int t = 0; t < 4; t++)
                    mma_16816(acc[f][t][0], acc[f][t][1], acc[f][t][2], acc[f][t][3],
                              a[f][0], a[f][1], a[f][2], a[f][3], b[t][0], b[t][1]);
        }
    }

    // ---- epilogue: write split partials, D[n][m] frag -> partial[split][m][n] ----
    float* pbase = g_partial + (size_t)split * M_DIM * N_DIM;
#pragma unroll
    for (int f = 0; f < 2; f++) {
        const int n_r = nbase + warp * 32 + 16 * f + lane4;
#pragma unroll
        for (int t = 0; t < 4; t++) {
            const int m_c = 8 * t + 2 * (lane & 3);
            float* p = pbase + (size_t)m_c * N_DIM + n_r;
            p[0]         = acc[f][t][0];   // (n_r,   m_c)
            p[N_DIM]     = acc[f][t][1];   // (n_r,   m_c+1)
            p[8]         = acc[f][t][2];   // (n_r+8, m_c)
            p[N_DIM + 8] = acc[f][t][3];   // (n_r+8, m_c+1)
        }
    }
}

__global__ void __launch_bounds__(256)
marlin_w4a16_reduce(const float* __restrict__ bias, float* __restrict__ out) {
    const int v = blockIdx.x * 256 + threadIdx.x;   // float4 index, n fastest
    const int e = v * 4;
    const int n = e & (N_DIM - 1);
    float4 s = make_float4(0.f, 0.f, 0.f, 0.f);
#pragma unroll
    for (int sp = 0; sp < SPLITS; sp++) {
        float4 p = *reinterpret_cast<const float4*>(
            &g_partial[(size_t)sp * (M_DIM * N_DIM) + e]);
        s.x += p.x; s.y += p.y; s.z += p.z; s.w += p.w;
    }
    float4 b = *reinterpret_cast<const float4*>(bias + n);
    s.x += b.x; s.y += b.y; s.z += b.z; s.w += b.w;
    *reinterpret_cast<float4*>(out + e) = s;
}

extern "C" void kernel_launch(void* const* d_in, const int* in_sizes, int n_in,
                              void* d_out, int out_size) {
    const float* A      = (const float*)d_in[0];
    const int*   qw     = (const int*)d_in[1];
    const float* scales = (const float*)d_in[2];
    const float* bias   = (const float*)d_in[3];
    float* out = (float*)d_out;

    dim3 grid(NTILES, SPLITS);
    marlin_w4a16_main<<<grid, THREADS>>>(A, qw, scales);
    marlin_w4a16_reduce<<<(M_DIM * N_DIM) / (256 * 4), 256>>>(bias, out);
}